// round 17
// baseline (speedup 1.0000x reference)
#include <cuda_runtime.h>
#include <cuda_bf16.h>
#include <math.h>
#include <stdint.h>

#define NQ 75
#define NS 25
#define NU 64
#define NALL 164
#define H1 84
#define H2 42
#define H3 21
#define PP 441
#define KCLS 5
#define SHOT 5
#define MSUP (SHOT*PP)          // 2205
#define MAUG (MSUP + 10*PP)     // 6615
#define BCOLS 6656              // 52*128
#define QROWS (NQ*PP)           // 33075
#define QPAD  33152             // 259*128
#define UROWS (NU*PP)           // 28224
#define UPAD  28288             // 221*128
#define SELN 10
#define NEGINF -3.4e38f
#define CT2 128
#define BROW 144

typedef unsigned long long ull;

__device__ float g_bufA[(size_t)NALL*64*H1*H1];
__device__ float g_bufC[(size_t)NALL*64*H2*H2];
__device__ float g_bufD[(size_t)NALL*64*H3*H3];
__device__ float g_bufE[(size_t)NALL*64*H3*H3];
__device__ float g_bufB[(size_t)NALL*64*H2*H2];
__device__ float g_rinv[(size_t)NALL*PP];
__device__ __nv_bfloat16 g_qbf[(size_t)QPAD*64];
__device__ __nv_bfloat16 g_ubf[(size_t)UPAD*64];
__device__ __nv_bfloat16 g_bankbf[(size_t)KCLS*BCOLS*64];
__device__ float g_rowsum[(size_t)KCLS*QPAD];
__device__ float g_stats[3*64*2];
__device__ float g_simu[NU*KCLS];
__device__ int   g_selidx[KCLS*SELN];

__device__ __forceinline__ float* bufPtr(int s){
    switch(s){
        case 0: return g_bufA; case 1: return g_bufB; case 2: return g_bufC;
        case 3: return g_bufD; default: return g_bufE;
    }
}
__device__ __forceinline__ int groupOf(int n){ return (n < NQ) ? 0 : ((n < NQ+NS) ? 1 : 2); }

__device__ __forceinline__ void cpasync16(uint32_t dst, const void* src){
    asm volatile("cp.async.cg.shared.global [%0], [%1], 16;\n" :: "r"(dst), "l"(src));
}
#define CP_COMMIT() asm volatile("cp.async.commit_group;\n" ::: "memory")
#define CP_WAIT0()  asm volatile("cp.async.wait_group 0;\n" ::: "memory")

// ---- packed fp32x2 helpers (sm_100+ FFMA2 path) ----
__device__ __forceinline__ ull pk2(float lo, float hi){
    ull r; asm("mov.b64 %0, {%1,%2};" : "=l"(r) : "f"(lo), "f"(hi)); return r;
}
__device__ __forceinline__ void fma2(ull& d, ull a, ull b){
    asm("fma.rn.f32x2 %0, %1, %2, %0;" : "+l"(d) : "l"(a), "l"(b));
}
__device__ __forceinline__ void upk2(ull v, float& lo, float& hi){
    asm("mov.b64 {%0,%1}, %2;" : "=f"(lo), "=f"(hi) : "l"(v));
}

__device__ __forceinline__ void ins3(float v, float& t0, float& t1, float& t2){
    if (v > t2){
        if (v > t0){ t2 = t1; t1 = t0; t0 = v; }
        else if (v > t1){ t2 = t1; t1 = v; }
        else t2 = v;
    }
}

// ---------- conv1: 3->64, 84x84 SAME ; oc-paired FFMA2 ----------
__global__ void conv1_kernel(const float* __restrict__ in1, const float* __restrict__ in2,
                             const float* __restrict__ in3, const float* __restrict__ w)
{
    __shared__ float2 sW2[32*28];     // [ocpair][tap], taps 0..26 used
    __shared__ float sIn[3*18*18];
    const int n = blockIdx.z;
    const int gx0 = blockIdx.x*16, gy0 = blockIdx.y*16;
    const int tx = threadIdx.x, ty = threadIdx.y;
    const int tid = ty*16 + tx;
    const float* img = (n < NQ)    ? (in1 + (size_t)n*3*H1*H1)
                     : (n < NQ+NS) ? (in2 + (size_t)(n-NQ)*3*H1*H1)
                                   : (in3 + (size_t)(n-NQ-NS)*3*H1*H1);
    for (int i = tid; i < 32*27; i += 256){
        int p = i / 27, j = i % 27;
        sW2[p*28 + j] = make_float2(w[(2*p)*27 + j], w[(2*p+1)*27 + j]);
    }
    for (int i = tid; i < 3*18*18; i += 256) {
        int c = i / 324, rem = i % 324, r = rem/18, cc = rem%18;
        int gy = gy0 - 1 + r, gx = gx0 - 1 + cc;
        sIn[i] = (gy>=0 && gy<H1 && gx>=0 && gx<H1) ? img[((size_t)c*H1+gy)*H1+gx] : 0.f;
    }
    __syncthreads();
    int ox = gx0+tx, oy = gy0+ty;
    if (ox >= H1 || oy >= H1) return;
    ull vd[27];
#pragma unroll
    for (int c=0;c<3;c++)
#pragma unroll
      for (int dy=0;dy<3;dy++)
#pragma unroll
        for (int dx=0;dx<3;dx++){
          float x = sIn[c*324 + (ty+dy)*18 + (tx+dx)];
          vd[c*9+dy*3+dx] = pk2(x, x);
        }
#pragma unroll 2
    for (int p=0; p<32; p++){
        const ull* wo = (const ull*)(sW2 + p*28);
        ull acc = 0ull;
#pragma unroll
        for (int jj=0; jj<13; jj++){
            ulonglong2 ww = *(const ulonglong2*)(wo + 2*jj);
            fma2(acc, vd[2*jj],   ww.x);
            fma2(acc, vd[2*jj+1], ww.y);
        }
        fma2(acc, vd[26], wo[26]);
        float lo, hi; upk2(acc, lo, hi);
        g_bufA[(((size_t)n*64 + 2*p  )*H1+oy)*H1+ox] = lo;
        g_bufA[(((size_t)n*64 + 2*p+1)*H1+oy)*H1+ox] = hi;
    }
}

// ---------- conv 64->64 3x3 SAME (16-wide tiles, conv2 @42) ; row-paired FFMA2 ----------
template<int RPT>   // RPT even
__global__ void conv64_kernel(int inSel, int outSel, const float* __restrict__ wt, int H, int W)
{
    extern __shared__ float sm[];
    float2* sW2 = (float2*)sm;        // [16 oc][8 ic][10 pairs] = 1280 float2 (10240B)
    float*  sIn = sm + 2560;          // [8 ic][HALO]
    constexpr int TH   = 8*RPT;
    constexpr int HALO = (TH+2)*18;
    constexpr int NP   = RPT/2;       // acc pairs per oc
    const int z   = blockIdx.z;
    const int n   = z >> 2;
    const int ocg = z & 3;
    const int gx0 = blockIdx.x*16;
    const int gy0 = blockIdx.y*TH;
    const int tx = threadIdx.x, ty = threadIdx.y;
    const int tid = ty*16 + tx;
    const int half = ty >> 3;
    const int tyr  = ty & 7;
    const int oyb = gy0 + tyr*RPT;
    const int ox  = gx0 + tx;
    const bool anyValid = (ox < W) && (oyb < H);
    const float* inN  = bufPtr(inSel)  + (size_t)n*64*H*W;
    float*       outN = bufPtr(outSel) + (size_t)n*64*H*W;

    ull accp[8][NP];
#pragma unroll
    for (int o=0;o<8;o++)
#pragma unroll
      for (int j=0;j<NP;j++) accp[o][j]=0ull;

    for (int cc = 0; cc < 8; ++cc) {
        __syncthreads();
        for (int i = tid; i < 1152; i += 256) {
            int o = i / 72, rem = i % 72;
            int ic = rem / 9, j = rem % 9;
            float wv = wt[(size_t)(ocg*16+o)*576 + cc*72 + rem];
            sW2[o*80 + ic*10 + j] = make_float2(wv, wv);
        }
        for (int i = tid; i < 8*HALO; i += 256) {
            int c = i / HALO, rem = i % HALO, r = rem/18, col = rem%18;
            int gy = gy0-1+r, gx = gx0-1+col;
            float v = 0.f;
            if (gy>=0 && gy<H && gx>=0 && gx<W)
                v = inN[((size_t)(cc*8+c)*H+gy)*W+gx];
            sIn[i] = v;
        }
        __syncthreads();
        if (anyValid) {
            for (int ic=0; ic<8; ++ic) {
                float v[RPT+2][3];
                const float* sp = sIn + ic*HALO + (tyr*RPT)*18 + tx;
#pragma unroll
                for (int r=0;r<RPT+2;r++)
#pragma unroll
                  for (int d=0;d<3;d++) v[r][d] = sp[r*18+d];
                // row pairs: start s = 0..RPT, 3 cols
                ull P[RPT+1][3];
#pragma unroll
                for (int s=0;s<RPT+1;s++)
#pragma unroll
                  for (int d=0;d<3;d++) P[s][d] = pk2(v[s][d], v[s+1][d]);
                const ull* wBase = (const ull*)(sW2 + (half*8)*80 + ic*10);
#pragma unroll
                for (int o=0;o<8;o++){
                    const ull* wo = wBase + o*80;
                    ulonglong2 wa = *(const ulonglong2*)(wo);      // w0,w1
                    ulonglong2 wb = *(const ulonglong2*)(wo+2);    // w2,w3
                    ulonglong2 wc = *(const ulonglong2*)(wo+4);    // w4,w5
                    ulonglong2 wd = *(const ulonglong2*)(wo+6);    // w6,w7
                    ull w8 = wo[8];
#pragma unroll
                    for (int j=0;j<NP;j++){
                        ull a = accp[o][j];
                        fma2(a, P[2*j  ][0], wa.x); fma2(a, P[2*j  ][1], wa.y); fma2(a, P[2*j  ][2], wb.x);
                        fma2(a, P[2*j+1][0], wb.y); fma2(a, P[2*j+1][1], wc.x); fma2(a, P[2*j+1][2], wc.y);
                        fma2(a, P[2*j+2][0], wd.x); fma2(a, P[2*j+2][1], wd.y); fma2(a, P[2*j+2][2], w8);
                        accp[o][j] = a;
                    }
                }
            }
        }
    }
    if (anyValid) {
#pragma unroll
        for (int o=0;o<8;o++){
            int oc = ocg*16 + half*8 + o;
#pragma unroll
            for (int j=0;j<NP;j++){
                float lo, hi; upk2(accp[o][j], lo, hi);
                int oy0 = oyb + 2*j;
                if (oy0   < H) outN[((size_t)oc*H+oy0  )*W+ox] = lo;
                if (oy0+1 < H) outN[((size_t)oc*H+oy0+1)*W+ox] = hi;
            }
        }
    }
}

// ---------- conv 64->64 3x3 SAME specialized for 21x21 ; row-paired FFMA2 ----------
__global__ void conv64_21_kernel(int inSel, int outSel, const float* __restrict__ wt)
{
    extern __shared__ float sm[];
    float2* sW2 = (float2*)sm;        // [16][8][10] float2 = 10240B
    float*  sIn = sm + 2560;          // [8 ic][26*23]
    const int HALO = 26*23;           // 598
    const int z = blockIdx.x;
    const int n = z >> 2, ocg = z & 3;
    const int tx = threadIdx.x;       // 0..20
    const int ty = threadIdx.y;       // 0..11
    const int tid = ty*21 + tx;
    const int half = ty / 6;
    const int tyr  = ty % 6;
    const int oyb = tyr*4;
    const float* inN  = bufPtr(inSel)  + (size_t)n*64*H3*H3;
    float*       outN = bufPtr(outSel) + (size_t)n*64*H3*H3;

    ull accp[8][2];
#pragma unroll
    for (int o=0;o<8;o++){ accp[o][0]=0ull; accp[o][1]=0ull; }

    for (int cc = 0; cc < 8; ++cc) {
        __syncthreads();
        for (int i = tid; i < 1152; i += 252) {
            int o = i / 72, rem = i % 72;
            int ic = rem / 9, j = rem % 9;
            float wv = wt[(size_t)(ocg*16+o)*576 + cc*72 + rem];
            sW2[o*80 + ic*10 + j] = make_float2(wv, wv);
        }
        for (int i = tid; i < 8*HALO; i += 252) {
            int c = i / HALO, rem = i % HALO, r = rem/23, col = rem%23;
            int gy = r-1, gx = col-1;
            float v = 0.f;
            if (gy>=0 && gy<H3 && gx>=0 && gx<H3)
                v = inN[((size_t)(cc*8+c)*H3+gy)*H3+gx];
            sIn[i] = v;
        }
        __syncthreads();
        for (int ic=0; ic<8; ++ic) {
            float v[6][3];
            const float* sp = sIn + ic*HALO + oyb*23 + tx;
#pragma unroll
            for (int r=0;r<6;r++)
#pragma unroll
              for (int d=0;d<3;d++) v[r][d] = sp[r*23+d];
            ull P[5][3];
#pragma unroll
            for (int s=0;s<5;s++)
#pragma unroll
              for (int d=0;d<3;d++) P[s][d] = pk2(v[s][d], v[s+1][d]);
            const ull* wBase = (const ull*)(sW2 + (half*8)*80 + ic*10);
#pragma unroll
            for (int o=0;o<8;o++){
                const ull* wo = wBase + o*80;
                ulonglong2 wa = *(const ulonglong2*)(wo);
                ulonglong2 wb = *(const ulonglong2*)(wo+2);
                ulonglong2 wc = *(const ulonglong2*)(wo+4);
                ulonglong2 wd = *(const ulonglong2*)(wo+6);
                ull w8 = wo[8];
#pragma unroll
                for (int j=0;j<2;j++){
                    ull a = accp[o][j];
                    fma2(a, P[2*j  ][0], wa.x); fma2(a, P[2*j  ][1], wa.y); fma2(a, P[2*j  ][2], wb.x);
                    fma2(a, P[2*j+1][0], wb.y); fma2(a, P[2*j+1][1], wc.x); fma2(a, P[2*j+1][2], wc.y);
                    fma2(a, P[2*j+2][0], wd.x); fma2(a, P[2*j+2][1], wd.y); fma2(a, P[2*j+2][2], w8);
                    accp[o][j] = a;
                }
            }
        }
    }
#pragma unroll
    for (int o=0;o<8;o++){
        int oc = ocg*16 + half*8 + o;
#pragma unroll
        for (int j=0;j<2;j++){
            float lo, hi; upk2(accp[o][j], lo, hi);
            int oy0 = oyb + 2*j;
            if (oy0   < H3) outN[((size_t)oc*H3+oy0  )*H3+tx] = lo;
            if (oy0+1 < H3) outN[((size_t)oc*H3+oy0+1)*H3+tx] = hi;
        }
    }
}

// ---------- BN stats: fp32 per-plane partials; float4 only when aligned ----------
__global__ void bn_stats_kernel(int sel, int HW)
{
    __shared__ double ssum[256], ssum2[256];
    const int ch = blockIdx.x, g = blockIdx.y;
    const int n0 = (g==0)?0:((g==1)?NQ:(NQ+NS));
    const int n1 = (g==0)?NQ:((g==1)?(NQ+NS):NALL);
    const int tid = threadIdx.x;
    const float* buf = bufPtr(sel);
    const bool vec = (HW & 3) == 0;
    double ds=0.0, ds2=0.0;
    for (int n=n0; n<n1; ++n) {
        const float* p = buf + ((size_t)n*64+ch)*HW;
        float s=0.f, s2=0.f;
        if (vec){
            const float4* p4 = (const float4*)p;
            const int HW4 = HW >> 2;
            for (int i=tid;i<HW4;i+=256){
                float4 x = p4[i];
                s  += x.x + x.y + x.z + x.w;
                s2 += x.x*x.x + x.y*x.y + x.z*x.z + x.w*x.w;
            }
        } else {
            for (int i=tid;i<HW;i+=256){
                float x = p[i]; s += x; s2 += x*x;
            }
        }
        ds += (double)s; ds2 += (double)s2;
    }
    ssum[tid]=ds; ssum2[tid]=ds2; __syncthreads();
    for (int st=128; st>0; st>>=1){
        if (tid<st){ ssum[tid]+=ssum[tid+st]; ssum2[tid]+=ssum2[tid+st]; }
        __syncthreads();
    }
    if (tid==0){
        double cnt = (double)(n1-n0)*HW;
        double mean = ssum[0]/cnt;
        double var  = ssum2[0]/cnt - mean*mean;
        g_stats[(g*64+ch)*2+0] = (float)mean;
        g_stats[(g*64+ch)*2+1] = (float)(1.0/sqrt(var + 1e-5));
    }
}

// ---------- BN + LeakyReLU (+pool) ----------
__global__ void bn_pool_kernel(int inSel, int outSel, const float* __restrict__ gamma,
                               const float* __restrict__ beta, int H, int W, int doPool)
{
    const int oH = doPool ? H/2 : H, oW = doPool ? W/2 : W;
    const size_t total = (size_t)NALL*64*oH*oW;
    const float* in = bufPtr(inSel);
    float* out = bufPtr(outSel);
    for (size_t idx = (size_t)blockIdx.x*blockDim.x + threadIdx.x; idx < total;
         idx += (size_t)gridDim.x*blockDim.x) {
        int ox = (int)(idx % oW); size_t t = idx / oW;
        int oy = (int)(t % oH);   t /= oH;
        int c  = (int)(t % 64);   int n = (int)(t / 64);
        int g = groupOf(n);
        float mean = g_stats[(g*64+c)*2+0], rsig = g_stats[(g*64+c)*2+1];
        float sc = gamma[c]*rsig;
        float sh = beta[c] - mean*sc;
        const float* p = in + ((size_t)n*64+c)*H*W;
        float r;
        if (doPool){
            float x0 = p[(size_t)(2*oy)*W + 2*ox  ]*sc+sh;
            float x1 = p[(size_t)(2*oy)*W + 2*ox+1]*sc+sh;
            float x2 = p[(size_t)(2*oy+1)*W + 2*ox  ]*sc+sh;
            float x3 = p[(size_t)(2*oy+1)*W + 2*ox+1]*sc+sh;
            x0 = x0>=0.f?x0:0.2f*x0; x1 = x1>=0.f?x1:0.2f*x1;
            x2 = x2>=0.f?x2:0.2f*x2; x3 = x3>=0.f?x3:0.2f*x3;
            r = fmaxf(fmaxf(x0,x1), fmaxf(x2,x3));
        } else {
            float x = p[(size_t)oy*W+ox]*sc+sh;
            r = x>=0.f?x:0.2f*x;
        }
        out[idx] = r;
    }
}

// ---------- descriptor inverse norms ----------
__global__ void norm_kernel()
{
    int img = blockIdx.x;
    for (int p = threadIdx.x; p < PP; p += blockDim.x){
        float ss = 0.f;
        const float* f = g_bufD + (size_t)img*64*PP + p;
#pragma unroll
        for (int c=0;c<64;c++){ float x = f[(size_t)c*PP]; ss += x*x; }
        g_rinv[(size_t)img*PP + p] = rsqrtf(ss);
    }
}

// ---------- bf16 descriptor buffers ----------
__global__ void fillbf_desc_kernel(int mode)
{
    const int pad = mode ? UPAD : QPAD;
    const int nrows = mode ? UROWS : QROWS;
    const int imgBase = mode ? (NQ+NS) : 0;
    __nv_bfloat16* dst = mode ? g_ubf : g_qbf;
    const size_t total = (size_t)pad*64;
    for (size_t i = (size_t)blockIdx.x*blockDim.x + threadIdx.x; i < total;
         i += (size_t)gridDim.x*blockDim.x) {
        int k = (int)(i & 63); int row = (int)(i >> 6);
        float v = 0.f;
        if (row < nrows){
            int img = imgBase + row / PP, p = row % PP;
            v = g_bufD[((size_t)img*64+k)*PP + p] * g_rinv[(size_t)img*PP + p];
        }
        dst[i] = __float2bfloat16(v);
    }
}
__global__ void fillbf_support_kernel()
{
    const size_t total = (size_t)KCLS*BCOLS*64;
    for (size_t i = (size_t)blockIdx.x*blockDim.x + threadIdx.x; i < total;
         i += (size_t)gridDim.x*blockDim.x) {
        int k = (int)(i & 63); size_t t = i >> 6;
        int col = (int)(t % BCOLS); int j = (int)(t / BCOLS);
        if (col < MSUP){
            int s = col / PP, p = col % PP;
            int img = NQ + j*SHOT + s;
            g_bankbf[i] = __float2bfloat16(
                g_bufD[((size_t)img*64+k)*PP + p] * g_rinv[(size_t)img*PP + p]);
        } else if (col >= MAUG){
            g_bankbf[i] = __float2bfloat16(0.f);
        }
    }
}
__global__ void fillbf_aug_kernel()
{
    const size_t total = (size_t)KCLS*(SELN*PP)*64;
    for (size_t i = (size_t)blockIdx.x*blockDim.x + threadIdx.x; i < total;
         i += (size_t)gridDim.x*blockDim.x) {
        int k = (int)(i & 63); size_t t = i >> 6;
        int a = (int)(t % (SELN*PP)); int j = (int)(t / (SELN*PP));
        int sel = a / PP, p = a % PP;
        int img = NQ + NS + g_selidx[j*SELN + sel];
        g_bankbf[(((size_t)j*BCOLS) + MSUP + a)*64 + k] = __float2bfloat16(
            g_bufD[((size_t)img*64+k)*PP + p] * g_rinv[(size_t)img*PP + p]);
    }
}

// ---------- unified mma.sync bf16 + register-resident top-3 ----------
__global__ void __launch_bounds__(256) mma_topk_kernel(int aSel, int cols)
{
    extern __shared__ char smc[];
    char* As = smc;
    char* Bs = smc + 18432;
    const int tid = threadIdx.x;
    const int wid = tid >> 5, lane = tid & 31;
    const int g = lane >> 2, tg = lane & 3;
    const int cls = blockIdx.y;
    const int row0 = blockIdx.x*128;
    const int ntiles = (cols + CT2 - 1)/CT2;

    uint32_t sA = (uint32_t)__cvta_generic_to_shared(As);
    uint32_t sB = (uint32_t)__cvta_generic_to_shared(Bs);

    const char* aG = (const char*)(aSel ? g_qbf : g_ubf) + (size_t)row0*128;
    for (int c = tid; c < 1024; c += 256){
        int col = c >> 3, part = c & 7;
        cpasync16(sA + (uint32_t)(col*BROW + part*16), aG + (size_t)col*128 + part*16);
    }
    const char* bG = (const char*)g_bankbf + (size_t)cls*BCOLS*128;
    for (int c = tid; c < 1024; c += 256){
        int col = c >> 3, part = c & 7;
        cpasync16(sB + (uint32_t)(col*BROW + part*16), bG + (size_t)col*128 + part*16);
    }
    CP_COMMIT(); CP_WAIT0();
    __syncthreads();

    uint32_t a[4][4];
    {
        const char* ar = As + (wid*16 + g)*BROW + tg*4;
#pragma unroll
        for (int kk=0; kk<4; kk++){
            a[kk][0] = *(const uint32_t*)(ar + kk*32);
            a[kk][1] = *(const uint32_t*)(ar + 8*BROW + kk*32);
            a[kk][2] = *(const uint32_t*)(ar + kk*32 + 16);
            a[kk][3] = *(const uint32_t*)(ar + 8*BROW + kk*32 + 16);
        }
    }

    float tA0=NEGINF, tA1=NEGINF, tA2=NEGINF;
    float tB0=NEGINF, tB1=NEGINF, tB2=NEGINF;

    for (int t = 0; t < ntiles; ++t){
        if (t+1 < ntiles){
            const char* bN = bG + (size_t)(t+1)*CT2*128;
            uint32_t bb = sB + (uint32_t)(((t+1)&1)*18432);
            for (int c = tid; c < 1024; c += 256){
                int col = c >> 3, part = c & 7;
                cpasync16(bb + (uint32_t)(col*BROW + part*16), bN + (size_t)col*128 + part*16);
            }
            CP_COMMIT();
        }
        const char* Bp = Bs + (t&1)*18432;
#pragma unroll 4
        for (int ns = 0; ns < 16; ++ns){
            const char* br = Bp + (ns*8 + g)*BROW + tg*4;
            float c0=0.f, c1=0.f, c2=0.f, c3=0.f;
#pragma unroll
            for (int kk=0; kk<4; kk++){
                uint32_t b0 = *(const uint32_t*)(br + kk*32);
                uint32_t b1 = *(const uint32_t*)(br + kk*32 + 16);
                asm volatile(
                    "mma.sync.aligned.m16n8k16.row.col.f32.bf16.bf16.f32 "
                    "{%0,%1,%2,%3}, {%4,%5,%6,%7}, {%8,%9}, {%0,%1,%2,%3};"
                    : "+f"(c0), "+f"(c1), "+f"(c2), "+f"(c3)
                    : "r"(a[kk][0]), "r"(a[kk][1]), "r"(a[kk][2]), "r"(a[kk][3]),
                      "r"(b0), "r"(b1));
            }
            const int colBase = t*CT2 + ns*8;
            if (colBase + 8 > cols){
                if (colBase + 2*tg     >= cols){ c0 = NEGINF; c2 = NEGINF; }
                if (colBase + 2*tg + 1 >= cols){ c1 = NEGINF; c3 = NEGINF; }
            }
            ins3(c0, tA0, tA1, tA2); ins3(c1, tA0, tA1, tA2);
            ins3(c2, tB0, tB1, tB2); ins3(c3, tB0, tB1, tB2);
        }
        if (t+1 < ntiles) CP_WAIT0();
        __syncthreads();
    }

#pragma unroll
    for (int off = 1; off <= 2; off <<= 1){
        float r0 = __shfl_xor_sync(0xffffffffu, tA0, off);
        float r1 = __shfl_xor_sync(0xffffffffu, tA1, off);
        float r2 = __shfl_xor_sync(0xffffffffu, tA2, off);
        ins3(r0, tA0, tA1, tA2); ins3(r1, tA0, tA1, tA2); ins3(r2, tA0, tA1, tA2);
        float s0 = __shfl_xor_sync(0xffffffffu, tB0, off);
        float s1 = __shfl_xor_sync(0xffffffffu, tB1, off);
        float s2 = __shfl_xor_sync(0xffffffffu, tB2, off);
        ins3(s0, tB0, tB1, tB2); ins3(s1, tB0, tB1, tB2); ins3(s2, tB0, tB1, tB2);
    }
    if (tg == 0){
        int row = row0 + wid*16 + g;
        g_rowsum[(size_t)cls*QPAD + row]     = tA0 + tA1 + tA2;
        g_rowsum[(size_t)cls*QPAD + row + 8] = tB0 + tB1 + tB2;
    }
}

// ---------- per-image deterministic sum ----------
__global__ void imgsum_kernel(float* __restrict__ outp, int useOut)
{
    __shared__ float s[128];
    const int img = blockIdx.x, cls = blockIdx.y;
    const int tid = threadIdx.x;
    const float* src = g_rowsum + (size_t)cls*QPAD + (size_t)img*PP;
    float v = 0.f;
    for (int i = tid; i < PP; i += 128) v += src[i];
    s[tid] = v; __syncthreads();
    for (int st=64; st>0; st>>=1){
        if (tid < st) s[tid] += s[tid+st];
        __syncthreads();
    }
    if (tid==0){
        float* dst = useOut ? outp : g_simu;
        dst[img*KCLS + cls] = s[0];
    }
}

// ---------- softmax + per-class top-10 (lowest-index ties) ----------
__global__ void select_kernel()
{
    __shared__ float pm[NU*KCLS];
    int tid = threadIdx.x;
    if (tid < NU){
        float v[KCLS]; float mx = NEGINF;
#pragma unroll
        for (int j=0;j<KCLS;j++){ v[j] = g_simu[tid*KCLS+j]; mx = fmaxf(mx, v[j]); }
        float s = 0.f;
#pragma unroll
        for (int j=0;j<KCLS;j++){ v[j] = expf(v[j]-mx); s += v[j]; }
#pragma unroll
        for (int j=0;j<KCLS;j++) pm[tid*KCLS+j] = v[j]/s;
    }
    __syncthreads();
    if (tid < KCLS){
        unsigned long long taken = 0ull;
        for (int i=0;i<SELN;i++){
            float best = NEGINF; int bi = 0;
            for (int b=0;b<NU;b++){
                if (taken & (1ull<<b)) continue;
                float val = pm[b*KCLS+tid];
                if (val > best){ best = val; bi = b; }
            }
            taken |= (1ull<<bi);
            g_selidx[tid*SELN+i] = bi;
        }
    }
}

extern "C" void kernel_launch(void* const* d_in, const int* in_sizes, int n_in,
                              void* d_out, int out_size)
{
    (void)in_sizes; (void)n_in; (void)out_size;
    // dict order: input1..3, w1, w2, w3, w4, g1, b1, g2, b2, g3, b3, g4, b4
    const float* in1 = (const float*)d_in[0];
    const float* in2 = (const float*)d_in[1];
    const float* in3 = (const float*)d_in[2];
    const float* w1  = (const float*)d_in[3];
    const float* w2  = (const float*)d_in[4];
    const float* w3  = (const float*)d_in[5];
    const float* w4  = (const float*)d_in[6];
    const float* gg1 = (const float*)d_in[7];
    const float* bb1 = (const float*)d_in[8];
    const float* gg2 = (const float*)d_in[9];
    const float* bb2 = (const float*)d_in[10];
    const float* gg3 = (const float*)d_in[11];
    const float* bb3 = (const float*)d_in[12];
    const float* gg4 = (const float*)d_in[13];
    const float* bb4 = (const float*)d_in[14];
    float* out = (float*)d_out;

    const int SM3  = 10240 + 8*(50*18)*4;    // conv64<6>: 39040B (TH=48)
    const int SM21 = 10240 + 8*598*4;        // conv64_21: 29376B
    const int SMM  = 3*18432;                // 55296B
    cudaFuncSetAttribute(conv64_kernel<6>,  cudaFuncAttributeMaxDynamicSharedMemorySize, SM3);
    cudaFuncSetAttribute(conv64_21_kernel,  cudaFuncAttributeMaxDynamicSharedMemorySize, SM21);
    cudaFuncSetAttribute(mma_topk_kernel,   cudaFuncAttributeMaxDynamicSharedMemorySize, SMM);

    dim3 blk(16,16);
    dim3 blk21(21,12);
    conv1_kernel<<<dim3(6,6,NALL), blk>>>(in1, in2, in3, w1);
    bn_stats_kernel<<<dim3(64,3), 256>>>(0, H1*H1);
    bn_pool_kernel<<<2048, 256>>>(0, 1, gg1, bb1, H1, H1, 1);
    conv64_kernel<6><<<dim3(3,1,NALL*4), blk, SM3>>>(1, 2, w2, H2, H2);
    bn_stats_kernel<<<dim3(64,3), 256>>>(2, H2*H2);
    bn_pool_kernel<<<2048, 256>>>(2, 3, gg2, bb2, H2, H2, 1);
    conv64_21_kernel<<<NALL*4, blk21, SM21>>>(3, 4, w3);
    bn_stats_kernel<<<dim3(64,3), 256>>>(4, H3*H3);
    bn_pool_kernel<<<2048, 256>>>(4, 3, gg3, bb3, H3, H3, 0);
    conv64_21_kernel<<<NALL*4, blk21, SM21>>>(3, 4, w4);
    bn_stats_kernel<<<dim3(64,3), 256>>>(4, H3*H3);
    bn_pool_kernel<<<2048, 256>>>(4, 3, gg4, bb4, H3, H3, 0);   // final feats in D

    norm_kernel<<<NALL, 256>>>();
    fillbf_desc_kernel<<<2048, 256>>>(0);
    fillbf_desc_kernel<<<2048, 256>>>(1);
    fillbf_support_kernel<<<2048, 256>>>();

    mma_topk_kernel<<<dim3(UPAD/128, KCLS), 256, SMM>>>(0, MSUP);
    imgsum_kernel<<<dim3(NU, KCLS), 128>>>(nullptr, 0);
    select_kernel<<<1, 64>>>();
    fillbf_aug_kernel<<<2048, 256>>>();

    mma_topk_kernel<<<dim3(QPAD/128, KCLS), 256, SMM>>>(1, MAUG);
    imgsum_kernel<<<dim3(NQ, KCLS), 128>>>(out, 1);
}